// round 12
// baseline (speedup 1.0000x reference)
#include <cuda_runtime.h>
#include <cuda_fp16.h>
#include <math.h>

#define N_NODES 100000
#define E_EDGES 1200000
#define EPS 1e-5f

// fast ELU: expm1 via single-MUFU exp (rel err ~1e-7 vs 1e-3 budget)
__device__ __forceinline__ float fast_elu(float y) {
    return (y > 0.0f) ? y : (__expf(y) - 1.0f);
}

// -------- scratch (device globals; no allocation allowed) --------
__device__ float g_A[N_NODES * 64];     // act buffer (aliased as __half for layers 2/3)
__device__ float g_C[N_NODES * 64];     // conv output (pre-BN, fp32 always)
__device__ float g_dinv[N_NODES];
__device__ int   g_deg[N_NODES];
__device__ int   g_rowptr[N_NODES + 1];
__device__ int   g_cursor[N_NODES];
__device__ int2  g_edge[E_EDGES];       // {src, bits(norm)} sorted by dst
__device__ int   g_partial[512];
__device__ float g_stats[384];          // 3 slices of 128: [0..63] sum, [64..127] sumsq

// ----------------- degree -----------------
__global__ void k_deg_count(const int* __restrict__ dst, int* deg, int e) {
    int i = blockIdx.x * blockDim.x + threadIdx.x;
    if (i < e) atomicAdd(&deg[dst[i]], 1);
}

// dinv (self-loop +1) + per-block partial sums of edge-degree + zero stats (fused)
__global__ void k_dinv_blocksums(const int* __restrict__ deg, float* dinv,
                                 int* partial, float* stats_zero, int n) {
    __shared__ int s[256];
    int i = blockIdx.x * 256 + threadIdx.x;
    int d = (i < n) ? deg[i] : 0;
    if (i < n) dinv[i] = rsqrtf((float)(d + 1));
    if (blockIdx.x == 0) {
        stats_zero[threadIdx.x] = 0.0f;
        stats_zero[threadIdx.x + 128] = 0.0f;
    } else if (blockIdx.x == 1 && threadIdx.x < 128) {
        stats_zero[threadIdx.x + 256] = 0.0f;
    }
    s[threadIdx.x] = (i < n) ? d : 0;
    __syncthreads();
    for (int off = 128; off > 0; off >>= 1) {
        if (threadIdx.x < off) s[threadIdx.x] += s[threadIdx.x + off];
        __syncthreads();
    }
    if (threadIdx.x == 0) partial[blockIdx.x] = s[0];
}

// rowptr + cursor; each block redundantly scans ALL chunk partials in shared.
__global__ void k_rowptr(const int* __restrict__ deg, const int* __restrict__ partial,
                         int* rowptr, int* cursor, int n, int nchunks) {
    __shared__ int sp[2][512];
    __shared__ int s[2][256];
    int t = threadIdx.x;
#pragma unroll
    for (int h = 0; h < 2; h++) {
        int idx = t + h * 256;
        sp[0][idx] = (idx < nchunks) ? partial[idx] : 0;
    }
    __syncthreads();
    int p = 0;
    for (int off = 1; off < 512; off <<= 1) {
#pragma unroll
        for (int h = 0; h < 2; h++) {
            int idx = t + h * 256;
            sp[p ^ 1][idx] = sp[p][idx] + ((idx >= off) ? sp[p][idx - off] : 0);
        }
        p ^= 1;
        __syncthreads();
    }
    int c = blockIdx.x;
    int blockOff = (c > 0) ? sp[p][c - 1] : 0;

    int i = c * 256 + t;
    int v = (i < n) ? deg[i] : 0;
    s[0][t] = v;
    __syncthreads();
    int q = 0;
    for (int off = 1; off < 256; off <<= 1) {
        s[q ^ 1][t] = s[q][t] + ((t >= off) ? s[q][t - off] : 0);
        q ^= 1;
        __syncthreads();
    }
    if (i < n) {
        int ex = blockOff + s[q][t] - v;
        rowptr[i] = ex;
        cursor[i] = ex;
        if (i == n - 1) rowptr[n] = blockOff + s[q][t];
    }
}

__global__ void k_place(const int* __restrict__ src, const int* __restrict__ dst,
                        const float* __restrict__ dinv, int* cursor,
                        int2* edge_sorted, int e) {
    int i = blockIdx.x * blockDim.x + threadIdx.x;
    if (i >= e) return;
    int s = src[i], d = dst[i];
    int pos = atomicAdd(&cursor[d], 1);
    float nv = __ldg(&dinv[s]) * __ldg(&dinv[d]);
    edge_sorted[pos] = make_int2(s, __float_as_int(nv));
}

// ----------------- FUSED layer, fp32 input (layer 1) -----------------
template <int FIN, int FOUT, int S>
__global__ void __launch_bounds__(256)
k_layer(const float* __restrict__ act, const int* __restrict__ rowptr,
        const int2* __restrict__ edges, const float* __restrict__ dinv,
        const float* __restrict__ W, const float* __restrict__ b,
        float* __restrict__ outc, float* __restrict__ stats, int n) {
    constexpr int G = FIN / 4;
    constexpr int GS = G * S;
    constexpr int OPL = FOUT / GS;
    __shared__ float sW[FIN * FOUT];
    __shared__ float sb[FOUT];
    __shared__ float sSum[FOUT], sSq[FOUT];
    for (int i = threadIdx.x; i < FIN * FOUT; i += 256) sW[i] = W[i];
    if (threadIdx.x < FOUT) {
        sb[threadIdx.x] = b[threadIdx.x];
        sSum[threadIdx.x] = 0.0f;
        sSq[threadIdx.x] = 0.0f;
    }
    __syncthreads();

    int gid = blockIdx.x * 256 + threadIdx.x;
    int node = gid / GS;
    int idx = gid & (GS - 1);
    int s = idx / G;
    int q = idx & (G - 1);
    bool active = (node < n);
    int lane = threadIdx.x & 31;

    float4 a0 = make_float4(0.f, 0.f, 0.f, 0.f), a1 = a0;
    if (active) {
        const float4* a4 = reinterpret_cast<const float4*>(act);
        if (s == 0) {
            float di = dinv[node];
            float di2 = di * di;
            float4 hv = a4[(size_t)node * G + q];
            a0.x = di2 * hv.x; a0.y = di2 * hv.y; a0.z = di2 * hv.z; a0.w = di2 * hv.w;
        }
        int beg = rowptr[node], end = rowptr[node + 1];
        int i = beg + s;
        for (; i + S < end; i += 2 * S) {
            int2 e0 = __ldg(&edges[i]);
            int2 e1 = __ldg(&edges[i + S]);
            float4 s0 = a4[(size_t)e0.x * G + q];
            float4 s1 = a4[(size_t)e1.x * G + q];
            float n0 = __int_as_float(e0.y), n1 = __int_as_float(e1.y);
            a0.x = fmaf(n0, s0.x, a0.x); a0.y = fmaf(n0, s0.y, a0.y);
            a0.z = fmaf(n0, s0.z, a0.z); a0.w = fmaf(n0, s0.w, a0.w);
            a1.x = fmaf(n1, s1.x, a1.x); a1.y = fmaf(n1, s1.y, a1.y);
            a1.z = fmaf(n1, s1.z, a1.z); a1.w = fmaf(n1, s1.w, a1.w);
        }
        if (i < end) {
            int2 e0 = __ldg(&edges[i]);
            float4 s0 = a4[(size_t)e0.x * G + q];
            float n0 = __int_as_float(e0.y);
            a0.x = fmaf(n0, s0.x, a0.x); a0.y = fmaf(n0, s0.y, a0.y);
            a0.z = fmaf(n0, s0.z, a0.z); a0.w = fmaf(n0, s0.w, a0.w);
        }
    }
    float in0 = a0.x + a1.x;
    float in1 = a0.y + a1.y;
    float in2 = a0.z + a1.z;
    float in3 = a0.w + a1.w;
    __syncwarp();
#pragma unroll
    for (int off = G; off < GS; off <<= 1) {
        in0 += __shfl_xor_sync(0xffffffffu, in0, off);
        in1 += __shfl_xor_sync(0xffffffffu, in1, off);
        in2 += __shfl_xor_sync(0xffffffffu, in2, off);
        in3 += __shfl_xor_sync(0xffffffffu, in3, off);
    }

    float o[OPL];
#pragma unroll
    for (int i = 0; i < OPL; i++) o[i] = sb[idx * OPL + i];
    int base = lane & ~(GS - 1);
#pragma unroll
    for (int r = 0; r < G; r++) {
        float x0 = __shfl_sync(0xffffffffu, in0, base + r);
        float x1 = __shfl_sync(0xffffffffu, in1, base + r);
        float x2 = __shfl_sync(0xffffffffu, in2, base + r);
        float x3 = __shfl_sync(0xffffffffu, in3, base + r);
        int k = r * 4;
#pragma unroll
        for (int i = 0; i < OPL; i++) {
            int col = idx * OPL + i;
            float t = o[i];
            t = fmaf(x0, sW[(k + 0) * FOUT + col], t);
            t = fmaf(x1, sW[(k + 1) * FOUT + col], t);
            t = fmaf(x2, sW[(k + 2) * FOUT + col], t);
            t = fmaf(x3, sW[(k + 3) * FOUT + col], t);
            o[i] = t;
        }
    }
    if (active) {
        float2 v = make_float2(o[0], o[1]);
        *reinterpret_cast<float2*>(outc + (size_t)node * FOUT + idx * OPL) = v;
    }

#pragma unroll
    for (int i = 0; i < OPL; i++) {
        float r = active ? fmaxf(o[i], 0.0f) : 0.0f;
        float s2 = r * r;
#pragma unroll
        for (int off = GS; off < 32; off <<= 1) {
            r += __shfl_xor_sync(0xffffffffu, r, off);
            s2 += __shfl_xor_sync(0xffffffffu, s2, off);
        }
        if (lane < GS) {
            atomicAdd(&sSum[idx * OPL + i], r);
            atomicAdd(&sSq[idx * OPL + i], s2);
        }
    }
    __syncthreads();
    if (threadIdx.x < FOUT) {
        atomicAdd(&stats[threadIdx.x], sSum[threadIdx.x]);
        atomicAdd(&stats[64 + threadIdx.x], sSq[threadIdx.x]);
    }
}

// ----------------- FUSED layer, fp16 input (layers 2/3) -----------------
// G = FIN/8 lanes of 16B (8 halfs) per node; S edge stripes; GS = G*S lanes/node.
template <int FIN, int FOUT, int S>
__global__ void __launch_bounds__(256)
k_layer_h(const __half* __restrict__ act, const int* __restrict__ rowptr,
          const int2* __restrict__ edges, const float* __restrict__ dinv,
          const float* __restrict__ W, const float* __restrict__ b,
          float* __restrict__ outc, float* __restrict__ stats, int n) {
    constexpr int G = FIN / 8;
    constexpr int GS = G * S;
    constexpr int OPL = FOUT / GS;
    __shared__ float sW[FIN * FOUT];
    __shared__ float sb[FOUT];
    __shared__ float sSum[FOUT], sSq[FOUT];
    for (int i = threadIdx.x; i < FIN * FOUT; i += 256) sW[i] = W[i];
    if (threadIdx.x < FOUT) {
        sb[threadIdx.x] = b[threadIdx.x];
        sSum[threadIdx.x] = 0.0f;
        sSq[threadIdx.x] = 0.0f;
    }
    __syncthreads();

    int gid = blockIdx.x * 256 + threadIdx.x;
    int node = gid / GS;
    int idx = gid & (GS - 1);
    int s = idx / G;
    int q = idx & (G - 1);
    bool active = (node < n);
    int lane = threadIdx.x & 31;

    float a0[8], a1[8];
#pragma unroll
    for (int j = 0; j < 8; j++) { a0[j] = 0.0f; a1[j] = 0.0f; }

    if (active) {
        const uint4* a4 = reinterpret_cast<const uint4*>(act);
        if (s == 0) {
            float di = dinv[node];
            float di2 = di * di;
            uint4 u = a4[(size_t)node * G + q];
            const __half2* h = reinterpret_cast<const __half2*>(&u);
#pragma unroll
            for (int j = 0; j < 4; j++) {
                float2 f = __half22float2(h[j]);
                a0[2 * j] = di2 * f.x;
                a0[2 * j + 1] = di2 * f.y;
            }
        }
        int beg = rowptr[node], end = rowptr[node + 1];
        int i = beg + s;
        for (; i + S < end; i += 2 * S) {
            int2 e0 = __ldg(&edges[i]);
            int2 e1 = __ldg(&edges[i + S]);
            uint4 u0 = a4[(size_t)e0.x * G + q];
            uint4 u1 = a4[(size_t)e1.x * G + q];
            float n0 = __int_as_float(e0.y), n1 = __int_as_float(e1.y);
            const __half2* h0 = reinterpret_cast<const __half2*>(&u0);
            const __half2* h1 = reinterpret_cast<const __half2*>(&u1);
#pragma unroll
            for (int j = 0; j < 4; j++) {
                float2 f0 = __half22float2(h0[j]);
                float2 f1 = __half22float2(h1[j]);
                a0[2 * j] = fmaf(n0, f0.x, a0[2 * j]);
                a0[2 * j + 1] = fmaf(n0, f0.y, a0[2 * j + 1]);
                a1[2 * j] = fmaf(n1, f1.x, a1[2 * j]);
                a1[2 * j + 1] = fmaf(n1, f1.y, a1[2 * j + 1]);
            }
        }
        if (i < end) {
            int2 e0 = __ldg(&edges[i]);
            uint4 u0 = a4[(size_t)e0.x * G + q];
            float n0 = __int_as_float(e0.y);
            const __half2* h0 = reinterpret_cast<const __half2*>(&u0);
#pragma unroll
            for (int j = 0; j < 4; j++) {
                float2 f0 = __half22float2(h0[j]);
                a0[2 * j] = fmaf(n0, f0.x, a0[2 * j]);
                a0[2 * j + 1] = fmaf(n0, f0.y, a0[2 * j + 1]);
            }
        }
    }
    float in[8];
#pragma unroll
    for (int j = 0; j < 8; j++) in[j] = a0[j] + a1[j];
    __syncwarp();
#pragma unroll
    for (int off = G; off < GS; off <<= 1) {
#pragma unroll
        for (int j = 0; j < 8; j++) in[j] += __shfl_xor_sync(0xffffffffu, in[j], off);
    }

    // warp GEMM: lane holds 8 input features [q*8, q*8+8); broadcast per r-round
    float o[OPL];
#pragma unroll
    for (int i = 0; i < OPL; i++) o[i] = sb[idx * OPL + i];
    int base = lane & ~(GS - 1);
#pragma unroll
    for (int r = 0; r < G; r++) {
        float x[8];
#pragma unroll
        for (int j = 0; j < 8; j++) x[j] = __shfl_sync(0xffffffffu, in[j], base + r);
        int k = r * 8;
#pragma unroll
        for (int i = 0; i < OPL; i++) {
            int col = idx * OPL + i;
            float t = o[i];
#pragma unroll
            for (int j = 0; j < 8; j++) t = fmaf(x[j], sW[(k + j) * FOUT + col], t);
            o[i] = t;
        }
    }
    if (active) {
        float2 v = make_float2(o[0], o[1]);
        *reinterpret_cast<float2*>(outc + (size_t)node * FOUT + idx * OPL) = v;
    }

#pragma unroll
    for (int i = 0; i < OPL; i++) {
        float r = active ? fmaxf(o[i], 0.0f) : 0.0f;
        float s2 = r * r;
#pragma unroll
        for (int off = GS; off < 32; off <<= 1) {
            r += __shfl_xor_sync(0xffffffffu, r, off);
            s2 += __shfl_xor_sync(0xffffffffu, s2, off);
        }
        if (lane < GS) {
            atomicAdd(&sSum[idx * OPL + i], r);
            atomicAdd(&sSq[idx * OPL + i], s2);
        }
    }
    __syncthreads();
    if (threadIdx.x < FOUT) {
        atomicAdd(&stats[threadIdx.x], sSum[threadIdx.x]);
        atomicAdd(&stats[64 + threadIdx.x], sSq[threadIdx.x]);
    }
}

// ----------------- relu + BN + ELU -> fp16 output -----------------
template <int F>
__global__ void k_bn_elu_h(const float* __restrict__ c, const float* __restrict__ stats_in,
                           const float* __restrict__ g, const float* __restrict__ bt,
                           __half2* __restrict__ act, int n) {
    __shared__ float smean[F], sscale[F], sbt[F];
    if (threadIdx.x < F) {
        int col = threadIdx.x;
        float inv_n = 1.0f / (float)n;
        float mean = stats_in[col] * inv_n;
        float var = stats_in[64 + col] * inv_n - mean * mean;
        smean[col] = mean;
        sscale[col] = rsqrtf(var + EPS) * g[col];
        sbt[col] = bt[col];
    }
    __syncthreads();
    int idx4 = blockIdx.x * blockDim.x + threadIdx.x;
    if (idx4 >= n * (F / 4)) return;
    float4 v = reinterpret_cast<const float4*>(c)[idx4];
    int col = (idx4 * 4) & (F - 1);
    float x0 = fast_elu((fmaxf(v.x, 0.0f) - smean[col + 0]) * sscale[col + 0] + sbt[col + 0]);
    float x1 = fast_elu((fmaxf(v.y, 0.0f) - smean[col + 1]) * sscale[col + 1] + sbt[col + 1]);
    float x2 = fast_elu((fmaxf(v.z, 0.0f) - smean[col + 2]) * sscale[col + 2] + sbt[col + 2]);
    float x3 = fast_elu((fmaxf(v.w, 0.0f) - smean[col + 3]) * sscale[col + 3] + sbt[col + 3]);
    act[idx4 * 2 + 0] = __floats2half2_rn(x0, x1);
    act[idx4 * 2 + 1] = __floats2half2_rn(x2, x3);
}

// ----------------- fused relu+BN+ELU + MLP + log_softmax (all regs, no spills) -----------------
__global__ void __launch_bounds__(128)
k_mlp(const float* __restrict__ c, const float* __restrict__ stats_in,
      const float* __restrict__ g, const float* __restrict__ bt,
      const float* __restrict__ Wf1, const float* __restrict__ bf1,
      const float* __restrict__ Wf2, const float* __restrict__ bf2,
      const float* __restrict__ Wf3, const float* __restrict__ bf3,
      float* __restrict__ out, int n) {
    __shared__ float sW1[64 * 32], sb1[32];
    __shared__ float sW2[32 * 16], sb2[16];
    __shared__ float sW3[16 * 2], sb3[2];
    __shared__ float smean[64], sscale[64], sbt[64];
    for (int i = threadIdx.x; i < 64 * 32; i += blockDim.x) sW1[i] = Wf1[i];
    for (int i = threadIdx.x; i < 32 * 16; i += blockDim.x) sW2[i] = Wf2[i];
    for (int i = threadIdx.x; i < 32; i += blockDim.x) sW3[i] = Wf3[i];
    if (threadIdx.x < 32) sb1[threadIdx.x] = bf1[threadIdx.x];
    if (threadIdx.x < 16) sb2[threadIdx.x] = bf2[threadIdx.x];
    if (threadIdx.x < 2) sb3[threadIdx.x] = bf3[threadIdx.x];
    if (threadIdx.x < 64) {
        int col = threadIdx.x;
        float inv_n = 1.0f / (float)n;
        float mean = stats_in[col] * inv_n;
        float var = stats_in[64 + col] * inv_n - mean * mean;
        smean[col] = mean;
        sscale[col] = rsqrtf(var + EPS) * g[col];
        sbt[col] = bt[col];
    }
    __syncthreads();
    int node = blockIdx.x * blockDim.x + threadIdx.x;
    if (node >= n) return;

    float t1[32];
#pragma unroll
    for (int j = 0; j < 32; j++) t1[j] = sb1[j];

    const float4* hp = reinterpret_cast<const float4*>(c + (size_t)node * 64);
#pragma unroll
    for (int k4 = 0; k4 < 16; k4++) {
        float4 v4 = hp[k4];
        float x0 = fast_elu((fmaxf(v4.x, 0.0f) - smean[k4 * 4 + 0]) * sscale[k4 * 4 + 0] + sbt[k4 * 4 + 0]);
        float x1 = fast_elu((fmaxf(v4.y, 0.0f) - smean[k4 * 4 + 1]) * sscale[k4 * 4 + 1] + sbt[k4 * 4 + 1]);
        float x2 = fast_elu((fmaxf(v4.z, 0.0f) - smean[k4 * 4 + 2]) * sscale[k4 * 4 + 2] + sbt[k4 * 4 + 2]);
        float x3 = fast_elu((fmaxf(v4.w, 0.0f) - smean[k4 * 4 + 3]) * sscale[k4 * 4 + 3] + sbt[k4 * 4 + 3]);
#pragma unroll
        for (int j = 0; j < 32; j++) {
            float t = t1[j];
            t = fmaf(x0, sW1[(k4 * 4 + 0) * 32 + j], t);
            t = fmaf(x1, sW1[(k4 * 4 + 1) * 32 + j], t);
            t = fmaf(x2, sW1[(k4 * 4 + 2) * 32 + j], t);
            t = fmaf(x3, sW1[(k4 * 4 + 3) * 32 + j], t);
            t1[j] = t;
        }
    }
#pragma unroll
    for (int j = 0; j < 32; j++) t1[j] = fast_elu(t1[j]);

    float t2[16];
#pragma unroll
    for (int j = 0; j < 16; j++) t2[j] = sb2[j];
#pragma unroll
    for (int k = 0; k < 32; k++) {
#pragma unroll
        for (int j = 0; j < 16; j++) t2[j] = fmaf(t1[k], sW2[k * 16 + j], t2[j]);
    }
#pragma unroll
    for (int j = 0; j < 16; j++) t2[j] = fast_elu(t2[j]);

    float o0 = sb3[0], o1 = sb3[1];
#pragma unroll
    for (int k = 0; k < 16; k++) {
        o0 = fmaf(t2[k], sW3[k * 2 + 0], o0);
        o1 = fmaf(t2[k], sW3[k * 2 + 1], o1);
    }
    float m = fmaxf(o0, o1);
    float lse = m + __logf(__expf(o0 - m) + __expf(o1 - m));
    out[node * 2 + 0] = o0 - lse;
    out[node * 2 + 1] = o1 - lse;
}

// ----------------- launch -----------------
extern "C" void kernel_launch(void* const* d_in, const int* in_sizes, int n_in,
                              void* d_out, int out_size) {
    const float* x   = (const float*)d_in[0];
    const int* eidx  = (const int*)d_in[1];
    const float* W1  = (const float*)d_in[2];
    const float* b1  = (const float*)d_in[3];
    const float* g1  = (const float*)d_in[4];
    const float* bt1 = (const float*)d_in[5];
    const float* W2  = (const float*)d_in[6];
    const float* b2  = (const float*)d_in[7];
    const float* g2  = (const float*)d_in[8];
    const float* bt2 = (const float*)d_in[9];
    const float* W3  = (const float*)d_in[10];
    const float* b3  = (const float*)d_in[11];
    const float* g3  = (const float*)d_in[12];
    const float* bt3 = (const float*)d_in[13];
    const float* Wf1 = (const float*)d_in[14];
    const float* bf1 = (const float*)d_in[15];
    const float* Wf2 = (const float*)d_in[16];
    const float* bf2 = (const float*)d_in[17];
    const float* Wf3 = (const float*)d_in[18];
    const float* bf3 = (const float*)d_in[19];
    float* out = (float*)d_out;

    const int n = in_sizes[0] / 4;
    const int e = in_sizes[1] / 2;
    const int* src = eidx;
    const int* dst = eidx + e;

    float *pA, *pC, *pDinv, *pStats;
    int *pDeg, *pRowptr, *pCursor, *pPartial;
    int2* pEdge;
    cudaGetSymbolAddress((void**)&pA, g_A);
    cudaGetSymbolAddress((void**)&pC, g_C);
    cudaGetSymbolAddress((void**)&pDinv, g_dinv);
    cudaGetSymbolAddress((void**)&pDeg, g_deg);
    cudaGetSymbolAddress((void**)&pRowptr, g_rowptr);
    cudaGetSymbolAddress((void**)&pCursor, g_cursor);
    cudaGetSymbolAddress((void**)&pEdge, g_edge);
    cudaGetSymbolAddress((void**)&pPartial, g_partial);
    cudaGetSymbolAddress((void**)&pStats, g_stats);
    float* pS0 = pStats;
    float* pS1 = pStats + 128;
    float* pS2 = pStats + 256;
    __half* pAh = reinterpret_cast<__half*>(pA);

    const int TB = 256;
    const int gn = (n + TB - 1) / TB;
    const int ge = (e + TB - 1) / TB;

    cudaMemsetAsync(pDeg, 0, (size_t)n * sizeof(int), 0);

    // degree / dinv(+zero stats) / rowptr(fused scan) / place
    k_deg_count<<<ge, TB>>>(dst, pDeg, e);
    k_dinv_blocksums<<<gn, TB>>>(pDeg, pDinv, pPartial, pStats, n);
    k_rowptr<<<gn, TB>>>(pDeg, pPartial, pRowptr, pCursor, n, gn);
    k_place<<<ge, TB>>>(src, dst, pDinv, pCursor, pEdge, e);

    // ---- layer 1: 4->16 fp32 input, 8 lanes/node ----
    k_layer<4, 16, 8><<<(n * 8 + TB - 1) / TB, TB>>>(x, pRowptr, pEdge, pDinv, W1, b1, pC, pS0, n);
    // ---- layer 2: bn_elu(16)->fp16, 16->32 half gather, 16 lanes/node ----
    k_bn_elu_h<16><<<(n * 4 + TB - 1) / TB, TB>>>(pC, pS0, g1, bt1, (__half2*)pAh, n);
    k_layer_h<16, 32, 8><<<(n * 16 + TB - 1) / TB, TB>>>(pAh, pRowptr, pEdge, pDinv, W2, b2, pC, pS1, n);
    // ---- layer 3: bn_elu(32)->fp16, 32->64 half gather, 32 lanes/node ----
    k_bn_elu_h<32><<<(n * 8 + TB - 1) / TB, TB>>>(pC, pS1, g2, bt2, (__half2*)pAh, n);
    k_layer_h<32, 64, 8><<<(n * 32 + TB - 1) / TB, TB>>>(pAh, pRowptr, pEdge, pDinv, W3, b3, pC, pS2, n);

    // ---- bn_elu of layer3 + MLP head + log_softmax (fp32 path) ----
    k_mlp<<<(n + 127) / 128, 128>>>(pC, pS2, g3, bt3, Wf1, bf1, Wf2, bf2, Wf3, bf3, out, n);
}

// round 13
// speedup vs baseline: 1.1940x; 1.1940x over previous
#include <cuda_runtime.h>
#include <math.h>

#define N_NODES 100000
#define E_EDGES 1200000
#define EPS 1e-5f

// fast ELU: expm1 via single-MUFU exp (rel err ~1e-7 vs 1e-3 budget)
__device__ __forceinline__ float fast_elu(float y) {
    return (y > 0.0f) ? y : (__expf(y) - 1.0f);
}

// -------- scratch (device globals; no allocation allowed) --------
__device__ float g_A[N_NODES * 64];     // act' (dinv-prescaled activations) / x'
__device__ float g_C[N_NODES * 64];     // conv output (pre-BN)
__device__ float g_dinv[N_NODES];
__device__ int   g_deg[N_NODES];        // edge in-degree (memset to 0 each run)
__device__ int   g_rowptr[N_NODES + 1];
__device__ int   g_cursor[N_NODES];
__device__ int   g_esrc[E_EDGES];       // src ids sorted by dst (4B records!)
__device__ int   g_partial[512];
__device__ float g_stats[384];          // 3 slices of 128: [0..63] sum, [64..127] sumsq

// ----------------- degree -----------------
__global__ void k_deg_count(const int* __restrict__ dst, int* deg, int e) {
    int i = blockIdx.x * blockDim.x + threadIdx.x;
    if (i < e) atomicAdd(&deg[dst[i]], 1);
}

// dinv + x' = dinv*x (layer-1 prescale) + per-block degree sums + zero stats
__global__ void k_dinv_blocksums(const int* __restrict__ deg, const float* __restrict__ x,
                                 float* dinv, float* xs,
                                 int* partial, float* stats_zero, int n) {
    __shared__ int s[256];
    int i = blockIdx.x * 256 + threadIdx.x;
    int d = (i < n) ? deg[i] : 0;
    if (i < n) {
        float di = rsqrtf((float)(d + 1));
        dinv[i] = di;
        float4 xv = reinterpret_cast<const float4*>(x)[i];
        float4 o = make_float4(di * xv.x, di * xv.y, di * xv.z, di * xv.w);
        reinterpret_cast<float4*>(xs)[i] = o;
    }
    if (blockIdx.x == 0) {
        stats_zero[threadIdx.x] = 0.0f;
        stats_zero[threadIdx.x + 128] = 0.0f;
    } else if (blockIdx.x == 1 && threadIdx.x < 128) {
        stats_zero[threadIdx.x + 256] = 0.0f;
    }
    s[threadIdx.x] = (i < n) ? d : 0;
    __syncthreads();
    for (int off = 128; off > 0; off >>= 1) {
        if (threadIdx.x < off) s[threadIdx.x] += s[threadIdx.x + off];
        __syncthreads();
    }
    if (threadIdx.x == 0) partial[blockIdx.x] = s[0];
}

// rowptr + cursor; each block redundantly scans ALL chunk partials in shared.
__global__ void k_rowptr(const int* __restrict__ deg, const int* __restrict__ partial,
                         int* rowptr, int* cursor, int n, int nchunks) {
    __shared__ int sp[2][512];
    __shared__ int s[2][256];
    int t = threadIdx.x;
#pragma unroll
    for (int h = 0; h < 2; h++) {
        int idx = t + h * 256;
        sp[0][idx] = (idx < nchunks) ? partial[idx] : 0;
    }
    __syncthreads();
    int p = 0;
    for (int off = 1; off < 512; off <<= 1) {
#pragma unroll
        for (int h = 0; h < 2; h++) {
            int idx = t + h * 256;
            sp[p ^ 1][idx] = sp[p][idx] + ((idx >= off) ? sp[p][idx - off] : 0);
        }
        p ^= 1;
        __syncthreads();
    }
    int c = blockIdx.x;
    int blockOff = (c > 0) ? sp[p][c - 1] : 0;

    int i = c * 256 + t;
    int v = (i < n) ? deg[i] : 0;
    s[0][t] = v;
    __syncthreads();
    int q = 0;
    for (int off = 1; off < 256; off <<= 1) {
        s[q ^ 1][t] = s[q][t] + ((t >= off) ? s[q][t - off] : 0);
        q ^= 1;
        __syncthreads();
    }
    if (i < n) {
        int ex = blockOff + s[q][t] - v;
        rowptr[i] = ex;
        cursor[i] = ex;
        if (i == n - 1) rowptr[n] = blockOff + s[q][t];
    }
}

// place edges, 4B records (no norm needed: activations are dinv-prescaled)
__global__ void k_place(const int* __restrict__ src, const int* __restrict__ dst,
                        int* cursor, int* esrc, int e) {
    int i = blockIdx.x * blockDim.x + threadIdx.x;
    if (i >= e) return;
    int pos = atomicAdd(&cursor[dst[i]], 1);
    esrc[pos] = src[i];
}

// ----------------- FUSED layer: grid-stride gather + warp GEMM + register stats -----------------
// act' rows are dinv-prescaled. out[d] = W^T( dinv[d] * (act'[d] + sum_{s->d} act'[s]) ) + b
// GS = G*S lanes per node; stats accumulated in registers, flushed once per thread.
template <int FIN, int FOUT, int S>
__global__ void __launch_bounds__(256)
k_layer(const float* __restrict__ act, const int* __restrict__ rowptr,
        const int* __restrict__ esrc, const float* __restrict__ dinv,
        const float* __restrict__ W, const float* __restrict__ b,
        float* __restrict__ outc, float* __restrict__ stats, int n) {
    constexpr int G = FIN / 4;
    constexpr int GS = G * S;
    constexpr int OPL = FOUT / GS;
    __shared__ float sW[FIN * FOUT];
    __shared__ float sb[FOUT];
    __shared__ float sSum[FOUT], sSq[FOUT];
    for (int i = threadIdx.x; i < FIN * FOUT; i += 256) sW[i] = W[i];
    if (threadIdx.x < FOUT) {
        sb[threadIdx.x] = b[threadIdx.x];
        sSum[threadIdx.x] = 0.0f;
        sSq[threadIdx.x] = 0.0f;
    }
    __syncthreads();

    const int tid = threadIdx.x;
    const int lane = tid & 31;
    const int idx = tid & (GS - 1);       // loop-invariant (stride % GS == 0)
    const int s = idx / G;
    const int q = idx & (G - 1);
    const int tnode = tid / GS;
    const int base_lane = lane & ~(GS - 1);
    const int stride = gridDim.x * 256;
    const float4* a4 = reinterpret_cast<const float4*>(act);

    float rSum[OPL], rSq[OPL];
#pragma unroll
    for (int i = 0; i < OPL; i++) { rSum[i] = 0.0f; rSq[i] = 0.0f; }

    const int total = n * GS;
    for (int bbase = blockIdx.x * 256; bbase < total; bbase += stride) {
        int node = bbase / GS + tnode;
        bool active = (node < n);

        float4 a0 = make_float4(0.f, 0.f, 0.f, 0.f), a1 = a0;
        float di = 0.0f;
        if (active) {
            di = dinv[node];
            if (s == 0) a0 = a4[(size_t)node * G + q];   // self-loop (prescaled)
            int beg = rowptr[node], end = rowptr[node + 1];
            int i = beg + s;
            for (; i + S < end; i += 2 * S) {
                int e0 = __ldg(&esrc[i]);
                int e1 = __ldg(&esrc[i + S]);
                float4 s0 = a4[(size_t)e0 * G + q];
                float4 s1 = a4[(size_t)e1 * G + q];
                a0.x += s0.x; a0.y += s0.y; a0.z += s0.z; a0.w += s0.w;
                a1.x += s1.x; a1.y += s1.y; a1.z += s1.z; a1.w += s1.w;
            }
            if (i < end) {
                int e0 = __ldg(&esrc[i]);
                float4 s0 = a4[(size_t)e0 * G + q];
                a0.x += s0.x; a0.y += s0.y; a0.z += s0.z; a0.w += s0.w;
            }
        }
        float in0 = (a0.x + a1.x) * di;
        float in1 = (a0.y + a1.y) * di;
        float in2 = (a0.z + a1.z) * di;
        float in3 = (a0.w + a1.w) * di;
        __syncwarp();
#pragma unroll
        for (int off = G; off < GS; off <<= 1) {
            in0 += __shfl_xor_sync(0xffffffffu, in0, off);
            in1 += __shfl_xor_sync(0xffffffffu, in1, off);
            in2 += __shfl_xor_sync(0xffffffffu, in2, off);
            in3 += __shfl_xor_sync(0xffffffffu, in3, off);
        }

        float o[OPL];
#pragma unroll
        for (int i = 0; i < OPL; i++) o[i] = sb[idx * OPL + i];
#pragma unroll
        for (int r = 0; r < G; r++) {
            float x0 = __shfl_sync(0xffffffffu, in0, base_lane + r);
            float x1 = __shfl_sync(0xffffffffu, in1, base_lane + r);
            float x2 = __shfl_sync(0xffffffffu, in2, base_lane + r);
            float x3 = __shfl_sync(0xffffffffu, in3, base_lane + r);
            int k = r * 4;
#pragma unroll
            for (int i = 0; i < OPL; i++) {
                int col = idx * OPL + i;
                float t = o[i];
                t = fmaf(x0, sW[(k + 0) * FOUT + col], t);
                t = fmaf(x1, sW[(k + 1) * FOUT + col], t);
                t = fmaf(x2, sW[(k + 2) * FOUT + col], t);
                t = fmaf(x3, sW[(k + 3) * FOUT + col], t);
                o[i] = t;
            }
        }
        if (active) {
            float2 v = make_float2(o[0], o[1]);
            *reinterpret_cast<float2*>(outc + (size_t)node * FOUT + idx * OPL) = v;
#pragma unroll
            for (int i = 0; i < OPL; i++) {
                float r = fmaxf(o[i], 0.0f);
                rSum[i] += r;
                rSq[i] = fmaf(r, r, rSq[i]);
            }
        }
    }

    // single flush per thread
#pragma unroll
    for (int i = 0; i < OPL; i++) {
        atomicAdd(&sSum[idx * OPL + i], rSum[i]);
        atomicAdd(&sSq[idx * OPL + i], rSq[i]);
    }
    __syncthreads();
    if (threadIdx.x < FOUT) {
        atomicAdd(&stats[threadIdx.x], sSum[threadIdx.x]);
        atomicAdd(&stats[64 + threadIdx.x], sSq[threadIdx.x]);
    }
}

// ----------------- relu + BN + ELU + dinv-prescale (elementwise, float4) -----------------
template <int F>
__global__ void k_bn_elu(const float* __restrict__ c, const float* __restrict__ stats_in,
                         const float* __restrict__ g, const float* __restrict__ bt,
                         const float* __restrict__ dinv, float* __restrict__ act, int n) {
    constexpr int Q = F / 4;
    __shared__ float smean[F], sscale[F], sbt[F];
    if (threadIdx.x < F) {
        int col = threadIdx.x;
        float inv_n = 1.0f / (float)n;
        float mean = stats_in[col] * inv_n;
        float var = stats_in[64 + col] * inv_n - mean * mean;
        smean[col] = mean;
        sscale[col] = rsqrtf(var + EPS) * g[col];
        sbt[col] = bt[col];
    }
    __syncthreads();
    int idx4 = blockIdx.x * blockDim.x + threadIdx.x;
    if (idx4 >= n * Q) return;
    int node = idx4 / Q;
    int col = (idx4 * 4) & (F - 1);
    float di = dinv[node];
    float4 v = reinterpret_cast<const float4*>(c)[idx4];
    float4 o;
    o.x = di * fast_elu((fmaxf(v.x, 0.0f) - smean[col + 0]) * sscale[col + 0] + sbt[col + 0]);
    o.y = di * fast_elu((fmaxf(v.y, 0.0f) - smean[col + 1]) * sscale[col + 1] + sbt[col + 1]);
    o.z = di * fast_elu((fmaxf(v.z, 0.0f) - smean[col + 2]) * sscale[col + 2] + sbt[col + 2]);
    o.w = di * fast_elu((fmaxf(v.w, 0.0f) - smean[col + 3]) * sscale[col + 3] + sbt[col + 3]);
    reinterpret_cast<float4*>(act)[idx4] = o;
}

// ----------------- fused relu+BN+ELU + MLP + log_softmax (all regs, no spills) -----------------
__global__ void __launch_bounds__(128)
k_mlp(const float* __restrict__ c, const float* __restrict__ stats_in,
      const float* __restrict__ g, const float* __restrict__ bt,
      const float* __restrict__ Wf1, const float* __restrict__ bf1,
      const float* __restrict__ Wf2, const float* __restrict__ bf2,
      const float* __restrict__ Wf3, const float* __restrict__ bf3,
      float* __restrict__ out, int n) {
    __shared__ float sW1[64 * 32], sb1[32];
    __shared__ float sW2[32 * 16], sb2[16];
    __shared__ float sW3[16 * 2], sb3[2];
    __shared__ float smean[64], sscale[64], sbt[64];
    for (int i = threadIdx.x; i < 64 * 32; i += blockDim.x) sW1[i] = Wf1[i];
    for (int i = threadIdx.x; i < 32 * 16; i += blockDim.x) sW2[i] = Wf2[i];
    for (int i = threadIdx.x; i < 32; i += blockDim.x) sW3[i] = Wf3[i];
    if (threadIdx.x < 32) sb1[threadIdx.x] = bf1[threadIdx.x];
    if (threadIdx.x < 16) sb2[threadIdx.x] = bf2[threadIdx.x];
    if (threadIdx.x < 2) sb3[threadIdx.x] = bf3[threadIdx.x];
    if (threadIdx.x < 64) {
        int col = threadIdx.x;
        float inv_n = 1.0f / (float)n;
        float mean = stats_in[col] * inv_n;
        float var = stats_in[64 + col] * inv_n - mean * mean;
        smean[col] = mean;
        sscale[col] = rsqrtf(var + EPS) * g[col];
        sbt[col] = bt[col];
    }
    __syncthreads();
    int node = blockIdx.x * blockDim.x + threadIdx.x;
    if (node >= n) return;

    float t1[32];
#pragma unroll
    for (int j = 0; j < 32; j++) t1[j] = sb1[j];

    const float4* hp = reinterpret_cast<const float4*>(c + (size_t)node * 64);
#pragma unroll
    for (int k4 = 0; k4 < 16; k4++) {
        float4 v4 = hp[k4];
        float x0 = fast_elu((fmaxf(v4.x, 0.0f) - smean[k4 * 4 + 0]) * sscale[k4 * 4 + 0] + sbt[k4 * 4 + 0]);
        float x1 = fast_elu((fmaxf(v4.y, 0.0f) - smean[k4 * 4 + 1]) * sscale[k4 * 4 + 1] + sbt[k4 * 4 + 1]);
        float x2 = fast_elu((fmaxf(v4.z, 0.0f) - smean[k4 * 4 + 2]) * sscale[k4 * 4 + 2] + sbt[k4 * 4 + 2]);
        float x3 = fast_elu((fmaxf(v4.w, 0.0f) - smean[k4 * 4 + 3]) * sscale[k4 * 4 + 3] + sbt[k4 * 4 + 3]);
#pragma unroll
        for (int j = 0; j < 32; j++) {
            float t = t1[j];
            t = fmaf(x0, sW1[(k4 * 4 + 0) * 32 + j], t);
            t = fmaf(x1, sW1[(k4 * 4 + 1) * 32 + j], t);
            t = fmaf(x2, sW1[(k4 * 4 + 2) * 32 + j], t);
            t = fmaf(x3, sW1[(k4 * 4 + 3) * 32 + j], t);
            t1[j] = t;
        }
    }
#pragma unroll
    for (int j = 0; j < 32; j++) t1[j] = fast_elu(t1[j]);

    float t2[16];
#pragma unroll
    for (int j = 0; j < 16; j++) t2[j] = sb2[j];
#pragma unroll
    for (int k = 0; k < 32; k++) {
#pragma unroll
        for (int j = 0; j < 16; j++) t2[j] = fmaf(t1[k], sW2[k * 16 + j], t2[j]);
    }
#pragma unroll
    for (int j = 0; j < 16; j++) t2[j] = fast_elu(t2[j]);

    float o0 = sb3[0], o1 = sb3[1];
#pragma unroll
    for (int k = 0; k < 16; k++) {
        o0 = fmaf(t2[k], sW3[k * 2 + 0], o0);
        o1 = fmaf(t2[k], sW3[k * 2 + 1], o1);
    }
    float m = fmaxf(o0, o1);
    float lse = m + __logf(__expf(o0 - m) + __expf(o1 - m));
    out[node * 2 + 0] = o0 - lse;
    out[node * 2 + 1] = o1 - lse;
}

// ----------------- launch -----------------
extern "C" void kernel_launch(void* const* d_in, const int* in_sizes, int n_in,
                              void* d_out, int out_size) {
    const float* x   = (const float*)d_in[0];
    const int* eidx  = (const int*)d_in[1];
    const float* W1  = (const float*)d_in[2];
    const float* b1  = (const float*)d_in[3];
    const float* g1  = (const float*)d_in[4];
    const float* bt1 = (const float*)d_in[5];
    const float* W2  = (const float*)d_in[6];
    const float* b2  = (const float*)d_in[7];
    const float* g2  = (const float*)d_in[8];
    const float* bt2 = (const float*)d_in[9];
    const float* W3  = (const float*)d_in[10];
    const float* b3  = (const float*)d_in[11];
    const float* g3  = (const float*)d_in[12];
    const float* bt3 = (const float*)d_in[13];
    const float* Wf1 = (const float*)d_in[14];
    const float* bf1 = (const float*)d_in[15];
    const float* Wf2 = (const float*)d_in[16];
    const float* bf2 = (const float*)d_in[17];
    const float* Wf3 = (const float*)d_in[18];
    const float* bf3 = (const float*)d_in[19];
    float* out = (float*)d_out;

    const int n = in_sizes[0] / 4;
    const int e = in_sizes[1] / 2;
    const int* src = eidx;
    const int* dst = eidx + e;

    float *pA, *pC, *pDinv, *pStats;
    int *pDeg, *pRowptr, *pCursor, *pPartial, *pEsrc;
    cudaGetSymbolAddress((void**)&pA, g_A);
    cudaGetSymbolAddress((void**)&pC, g_C);
    cudaGetSymbolAddress((void**)&pDinv, g_dinv);
    cudaGetSymbolAddress((void**)&pDeg, g_deg);
    cudaGetSymbolAddress((void**)&pRowptr, g_rowptr);
    cudaGetSymbolAddress((void**)&pCursor, g_cursor);
    cudaGetSymbolAddress((void**)&pEsrc, g_esrc);
    cudaGetSymbolAddress((void**)&pPartial, g_partial);
    cudaGetSymbolAddress((void**)&pStats, g_stats);
    float* pS0 = pStats;
    float* pS1 = pStats + 128;
    float* pS2 = pStats + 256;

    const int TB = 256;
    const int gn = (n + TB - 1) / TB;
    const int ge = (e + TB - 1) / TB;
    const int NBLK = 1184;   // ~8 blocks/SM, grid-stride layers

    cudaMemsetAsync(pDeg, 0, (size_t)n * sizeof(int), 0);

    // degree / dinv(+x' prescale +zero stats) / rowptr / place
    k_deg_count<<<ge, TB>>>(dst, pDeg, e);
    k_dinv_blocksums<<<gn, TB>>>(pDeg, x, pDinv, pA, pPartial, pStats, n);
    k_rowptr<<<gn, TB>>>(pDeg, pPartial, pRowptr, pCursor, n, gn);
    k_place<<<ge, TB>>>(src, dst, pCursor, pEsrc, e);

    // ---- layer 1: 4->16 (x' in g_A), 8 lanes/node ----
    k_layer<4, 16, 8><<<NBLK, TB>>>(pA, pRowptr, pEsrc, pDinv, W1, b1, pC, pS0, n);
    // ---- layer 2: 16->32, 16 lanes/node ----
    k_bn_elu<16><<<(n * 4 + TB - 1) / TB, TB>>>(pC, pS0, g1, bt1, pDinv, pA, n);
    k_layer<16, 32, 4><<<NBLK, TB>>>(pA, pRowptr, pEsrc, pDinv, W2, b2, pC, pS1, n);
    // ---- layer 3: 32->64, 32 lanes/node ----
    k_bn_elu<32><<<(n * 8 + TB - 1) / TB, TB>>>(pC, pS1, g2, bt2, pDinv, pA, n);
    k_layer<32, 64, 4><<<NBLK, TB>>>(pA, pRowptr, pEsrc, pDinv, W3, b3, pC, pS2, n);

    // ---- bn_elu of layer3 + MLP head + log_softmax ----
    k_mlp<<<(n + 127) / 128, 128>>>(pC, pS2, g3, bt3, Wf1, bf1, Wf2, bf2, Wf3, bf3, out, n);
}